// round 7
// baseline (speedup 1.0000x reference)
#include <cuda_runtime.h>
#include <cstdint>

// Zero-initialized device globals (no allocations allowed).
// g_flags bit0: any(((x+1)+1) >= 3)   -> chain halts at checker #1; speculative out is correct
// g_flags bit1: any(four-adds >= 3)   -> chain halts at checker #2
// Last-arriving block performs the (statistically never-taken) fixup and
// resets both globals so every graph replay is deterministic.
__device__ int g_flags;
__device__ unsigned int g_count;

#define THREADS 256
#define UNROLL  4
#define CHUNK   (THREADS * UNROLL)   // 1024 float4 = 16 KB per block-iteration

__global__ void __launch_bounds__(THREADS) scn_fused_kernel(
    const float4* __restrict__ x, float4* __restrict__ out, int n4)
{
    const int t = threadIdx.x;

    // Running max of o = (x+1)+1 over this thread's elements.
    float m = -3.402823466e+38f;

    const int nchunks = n4 / CHUNK;          // 8388608 / 1024 = 8192 (exact)

    for (int c = blockIdx.x; c < nchunks; c += gridDim.x) {
        const int base = c * CHUNK + t;

        // 4 independent coalesced LDG.128 within one dense 16 KB chunk.
        float4 v0 = x[base];
        float4 v1 = x[base + THREADS];
        float4 v2 = x[base + 2 * THREADS];
        float4 v3 = x[base + 3 * THREADS];

        float4 o0, o1, o2, o3;
        o0.x = (v0.x + 1.0f) + 1.0f;  o0.y = (v0.y + 1.0f) + 1.0f;
        o0.z = (v0.z + 1.0f) + 1.0f;  o0.w = (v0.w + 1.0f) + 1.0f;
        o1.x = (v1.x + 1.0f) + 1.0f;  o1.y = (v1.y + 1.0f) + 1.0f;
        o1.z = (v1.z + 1.0f) + 1.0f;  o1.w = (v1.w + 1.0f) + 1.0f;
        o2.x = (v2.x + 1.0f) + 1.0f;  o2.y = (v2.y + 1.0f) + 1.0f;
        o2.z = (v2.z + 1.0f) + 1.0f;  o2.w = (v2.w + 1.0f) + 1.0f;
        o3.x = (v3.x + 1.0f) + 1.0f;  o3.y = (v3.y + 1.0f) + 1.0f;
        o3.z = (v3.z + 1.0f) + 1.0f;  o3.w = (v3.w + 1.0f) + 1.0f;

        float ma = fmaxf(fmaxf(o0.x, o0.y), fmaxf(o0.z, o0.w));
        float mb = fmaxf(fmaxf(o1.x, o1.y), fmaxf(o1.z, o1.w));
        float mc = fmaxf(fmaxf(o2.x, o2.y), fmaxf(o2.z, o2.w));
        float md = fmaxf(fmaxf(o3.x, o3.y), fmaxf(o3.z, o3.w));
        m = fmaxf(m, fmaxf(fmaxf(ma, mb), fmaxf(mc, md)));

        out[base]               = o0;
        out[base + THREADS]     = o1;
        out[base + 2 * THREADS] = o2;
        out[base + 3 * THREADS] = o3;
    }

    // Generic tail (empty for this shape, kept for correctness).
    for (int i = nchunks * CHUNK + blockIdx.x * THREADS + t; i < n4;
         i += gridDim.x * THREADS) {
        float4 v = x[i];
        float4 o;
        o.x = (v.x + 1.0f) + 1.0f;  o.y = (v.y + 1.0f) + 1.0f;
        o.z = (v.z + 1.0f) + 1.0f;  o.w = (v.w + 1.0f) + 1.0f;
        m = fmaxf(m, fmaxf(fmaxf(o.x, o.y), fmaxf(o.z, o.w)));
        out[i] = o;
    }

    // fp add of a constant is monotone non-decreasing, so (bit-exact):
    //   any((o+1)+1 >= 3)  <=>  ((max(o)+1)+1) >= 3
    // Warp-level any-reduction of the thread-local max, then one shared word.
    m = fmaxf(m, __shfl_xor_sync(0xFFFFFFFFu, m, 16));
    m = fmaxf(m, __shfl_xor_sync(0xFFFFFFFFu, m, 8));
    m = fmaxf(m, __shfl_xor_sync(0xFFFFFFFFu, m, 4));
    m = fmaxf(m, __shfl_xor_sync(0xFFFFFFFFu, m, 2));
    m = fmaxf(m, __shfl_xor_sync(0xFFFFFFFFu, m, 1));

    __shared__ int s_f;
    __shared__ int s_last;
    if (t == 0) s_f = 0;
    __syncthreads();
    if ((t & 31) == 0) {
        int f = (m >= 3.0f ? 1 : 0) | ((((m + 1.0f) + 1.0f) >= 3.0f) ? 2 : 0);
        if (f) atomicOr(&s_f, f);
    }
    __syncthreads();

    if (t == 0) {
        int f = s_f;
        if (f) atomicOr(&g_flags, f);
        // Release: order this block's out[] stores + flag OR before the
        // arrival increment the last block acquires through.
        __threadfence();
        unsigned cnt = atomicAdd(&g_count, 1u);
        s_last = (cnt == gridDim.x - 1) ? 1 : 0;
    }
    __syncthreads();

    if (s_last) {
        __threadfence();  // acquire side
        int f = atomicOr(&g_flags, 0);

        if (!(f & 1)) {
            // Rare path (statistically never for this input): the chain
            // survived checker #1 — rewrite output with deeper-chain values.
            bool five = !(f & 2);
            for (int j = t; j < n4; j += THREADS) {
                float4 v = x[j];
                float4 o;
                o.x = (((v.x + 1.0f) + 1.0f) + 1.0f) + 1.0f;
                o.y = (((v.y + 1.0f) + 1.0f) + 1.0f) + 1.0f;
                o.z = (((v.z + 1.0f) + 1.0f) + 1.0f) + 1.0f;
                o.w = (((v.w + 1.0f) + 1.0f) + 1.0f) + 1.0f;
                if (five) { o.x += 1.0f; o.y += 1.0f; o.z += 1.0f; o.w += 1.0f; }
                out[j] = o;
            }
        }

        __syncthreads();
        if (t == 0) {
            g_flags = 0;
            __threadfence();
            g_count = 0u;
        }
    }
}

extern "C" void kernel_launch(void* const* d_in, const int* in_sizes, int n_in,
                              void* d_out, int out_size)
{
    const float4* x = (const float4*)d_in[0];
    float4* out = (float4*)d_out;
    int n = in_sizes[0];
    int n4 = n >> 2;  // 4096*8192 divisible by 4

    const int blocks = 148 * 8;  // full occupancy (8 × 256 thr = 2048/SM), dense chunks
    scn_fused_kernel<<<blocks, THREADS>>>(x, out, n4);
}

// round 8
// speedup vs baseline: 1.0006x; 1.0006x over previous
#include <cuda_runtime.h>
#include <cstdint>

// Zero-initialized device globals (no allocations allowed).
// g_flags bit0: any(((x+1)+1) >= 3)   -> chain halts at checker #1; speculative out is correct
// g_flags bit1: any(four-adds >= 3)   -> chain halts at checker #2
// Last-arriving block performs the (statistically never-taken) fixup and
// resets both globals so every graph replay is deterministic.
__device__ int g_flags;
__device__ unsigned int g_count;

#define THREADS 256
#define WARPS   (THREADS / 32)
#define UNROLL  4
#define CHUNK   (THREADS * UNROLL)   // 1024 float4 = 16 KB per block-iteration

__global__ void __launch_bounds__(THREADS) scn_fused_kernel(
    const float4* __restrict__ x, float4* __restrict__ out, int n4)
{
    const int t = threadIdx.x;

    // Running max of o = (x+1)+1 over this thread's elements.
    float m = -3.402823466e+38f;

    const int nchunks = n4 / CHUNK;          // 8388608 / 1024 = 8192 (exact)

    for (int c = blockIdx.x; c < nchunks; c += gridDim.x) {
        const int base = c * CHUNK + t;

        // 4 independent coalesced LDG.128 within one dense 16 KB chunk.
        float4 v0 = x[base];
        float4 v1 = x[base + THREADS];
        float4 v2 = x[base + 2 * THREADS];
        float4 v3 = x[base + 3 * THREADS];

        float4 o0, o1, o2, o3;
        o0.x = (v0.x + 1.0f) + 1.0f;  o0.y = (v0.y + 1.0f) + 1.0f;
        o0.z = (v0.z + 1.0f) + 1.0f;  o0.w = (v0.w + 1.0f) + 1.0f;
        o1.x = (v1.x + 1.0f) + 1.0f;  o1.y = (v1.y + 1.0f) + 1.0f;
        o1.z = (v1.z + 1.0f) + 1.0f;  o1.w = (v1.w + 1.0f) + 1.0f;
        o2.x = (v2.x + 1.0f) + 1.0f;  o2.y = (v2.y + 1.0f) + 1.0f;
        o2.z = (v2.z + 1.0f) + 1.0f;  o2.w = (v2.w + 1.0f) + 1.0f;
        o3.x = (v3.x + 1.0f) + 1.0f;  o3.y = (v3.y + 1.0f) + 1.0f;
        o3.z = (v3.z + 1.0f) + 1.0f;  o3.w = (v3.w + 1.0f) + 1.0f;

        float ma = fmaxf(fmaxf(o0.x, o0.y), fmaxf(o0.z, o0.w));
        float mb = fmaxf(fmaxf(o1.x, o1.y), fmaxf(o1.z, o1.w));
        float mc = fmaxf(fmaxf(o2.x, o2.y), fmaxf(o2.z, o2.w));
        float md = fmaxf(fmaxf(o3.x, o3.y), fmaxf(o3.z, o3.w));
        m = fmaxf(m, fmaxf(fmaxf(ma, mb), fmaxf(mc, md)));

        out[base]               = o0;
        out[base + THREADS]     = o1;
        out[base + 2 * THREADS] = o2;
        out[base + 3 * THREADS] = o3;
    }

    // Generic tail (empty for this exact shape, kept for correctness).
    for (int i = nchunks * CHUNK + blockIdx.x * THREADS + t; i < n4;
         i += gridDim.x * THREADS) {
        float4 v = x[i];
        float4 o;
        o.x = (v.x + 1.0f) + 1.0f;  o.y = (v.y + 1.0f) + 1.0f;
        o.z = (v.z + 1.0f) + 1.0f;  o.w = (v.w + 1.0f) + 1.0f;
        m = fmaxf(m, fmaxf(fmaxf(o.x, o.y), fmaxf(o.z, o.w)));
        out[i] = o;
    }

    // fp add of a constant is monotone non-decreasing, so (bit-exact):
    //   any((o+1)+1 >= 3)  <=>  ((max(o)+1)+1) >= 3
    bool ta = (m >= 3.0f);
    bool tb = (((m + 1.0f) + 1.0f) >= 3.0f);

    // Warp any-reduction, then combine the per-warp bits through shared.
    unsigned wa = __any_sync(0xFFFFFFFFu, ta);
    unsigned wb = __any_sync(0xFFFFFFFFu, tb);

    __shared__ unsigned char s_wf[WARPS];
    __shared__ int s_last;
    if ((t & 31) == 0)
        s_wf[t >> 5] = (unsigned char)((wa ? 1u : 0u) | (wb ? 2u : 0u));
    __syncthreads();

    if (t == 0) {
        int f = 0;
#pragma unroll
        for (int w = 0; w < WARPS; w++) f |= s_wf[w];
        if (f) atomicOr(&g_flags, f);
        // Release: order this block's out[] stores + flag OR before the
        // arrival increment the last block acquires through.
        __threadfence();
        unsigned cnt = atomicAdd(&g_count, 1u);
        s_last = (cnt == gridDim.x - 1) ? 1 : 0;
    }
    __syncthreads();

    if (s_last) {
        __threadfence();  // acquire side
        int f = atomicOr(&g_flags, 0);

        if (!(f & 1)) {
            // Rare path (statistically never for this input): the chain
            // survived checker #1 — rewrite output with deeper-chain values.
            bool five = !(f & 2);
            for (int j = t; j < n4; j += THREADS) {
                float4 v = x[j];
                float4 o;
                o.x = (((v.x + 1.0f) + 1.0f) + 1.0f) + 1.0f;
                o.y = (((v.y + 1.0f) + 1.0f) + 1.0f) + 1.0f;
                o.z = (((v.z + 1.0f) + 1.0f) + 1.0f) + 1.0f;
                o.w = (((v.w + 1.0f) + 1.0f) + 1.0f) + 1.0f;
                if (five) { o.x += 1.0f; o.y += 1.0f; o.z += 1.0f; o.w += 1.0f; }
                out[j] = o;
            }
        }

        __syncthreads();
        if (t == 0) {
            g_flags = 0;
            __threadfence();
            g_count = 0u;
        }
    }
}

extern "C" void kernel_launch(void* const* d_in, const int* in_sizes, int n_in,
                              void* d_out, int out_size)
{
    const float4* x = (const float4*)d_in[0];
    float4* out = (float4*)d_out;
    int n = in_sizes[0];
    int n4 = n >> 2;  // 4096*8192 divisible by 4

    const int blocks = 148 * 8;  // one full wave (8 × 256 thr = 2048/SM), dense chunks
    scn_fused_kernel<<<blocks, THREADS>>>(x, out, n4);
}

// round 9
// speedup vs baseline: 1.0430x; 1.0423x over previous
#include <cuda_runtime.h>
#include <cstdint>

// Zero-initialized device global (no allocations allowed).
// Single packed word: bits[0:16)=arrival count, bits[16:32)=count of blocks
// seeing any((x+1)+1 >= 3), bits[32:48)=count of blocks seeing any(4-adds >= 3).
// One relaxed 64-bit atomicAdd per block carries BOTH the flags and the
// arrival: the last arriver reconstructs final flags from (old + own delta),
// so no fences and no second atomic are needed. The fixup path never reads
// out[] (it rewrites from x), so out-stores require no cross-block ordering.
// Last block resets the word for the next graph replay (deterministic).
__device__ unsigned long long g_packed;

#define THREADS 256
#define WARPS   (THREADS / 32)
#define UNROLL  4
#define CHUNK   (THREADS * UNROLL)   // 1024 float4 = 16 KB per block-iteration

#define A_INC (1ULL << 16)
#define B_INC (1ULL << 32)

__global__ void __launch_bounds__(THREADS) scn_fused_kernel(
    const float4* __restrict__ x, float4* __restrict__ out, int n4)
{
    const int t = threadIdx.x;

    // Running max of o = (x+1)+1 over this thread's elements.
    float m = -3.402823466e+38f;

    const int nchunks = n4 / CHUNK;          // 8388608 / 1024 = 8192 (exact)

    for (int c = blockIdx.x; c < nchunks; c += gridDim.x) {
        const int base = c * CHUNK + t;

        // 4 independent coalesced LDG.128 within one dense 16 KB chunk.
        float4 v0 = x[base];
        float4 v1 = x[base + THREADS];
        float4 v2 = x[base + 2 * THREADS];
        float4 v3 = x[base + 3 * THREADS];

        float4 o0, o1, o2, o3;
        o0.x = (v0.x + 1.0f) + 1.0f;  o0.y = (v0.y + 1.0f) + 1.0f;
        o0.z = (v0.z + 1.0f) + 1.0f;  o0.w = (v0.w + 1.0f) + 1.0f;
        o1.x = (v1.x + 1.0f) + 1.0f;  o1.y = (v1.y + 1.0f) + 1.0f;
        o1.z = (v1.z + 1.0f) + 1.0f;  o1.w = (v1.w + 1.0f) + 1.0f;
        o2.x = (v2.x + 1.0f) + 1.0f;  o2.y = (v2.y + 1.0f) + 1.0f;
        o2.z = (v2.z + 1.0f) + 1.0f;  o2.w = (v2.w + 1.0f) + 1.0f;
        o3.x = (v3.x + 1.0f) + 1.0f;  o3.y = (v3.y + 1.0f) + 1.0f;
        o3.z = (v3.z + 1.0f) + 1.0f;  o3.w = (v3.w + 1.0f) + 1.0f;

        float ma = fmaxf(fmaxf(o0.x, o0.y), fmaxf(o0.z, o0.w));
        float mb = fmaxf(fmaxf(o1.x, o1.y), fmaxf(o1.z, o1.w));
        float mc = fmaxf(fmaxf(o2.x, o2.y), fmaxf(o2.z, o2.w));
        float md = fmaxf(fmaxf(o3.x, o3.y), fmaxf(o3.z, o3.w));
        m = fmaxf(m, fmaxf(fmaxf(ma, mb), fmaxf(mc, md)));

        out[base]               = o0;
        out[base + THREADS]     = o1;
        out[base + 2 * THREADS] = o2;
        out[base + 3 * THREADS] = o3;
    }

    // Generic tail (empty for this exact shape, kept for correctness).
    for (int i = nchunks * CHUNK + blockIdx.x * THREADS + t; i < n4;
         i += gridDim.x * THREADS) {
        float4 v = x[i];
        float4 o;
        o.x = (v.x + 1.0f) + 1.0f;  o.y = (v.y + 1.0f) + 1.0f;
        o.z = (v.z + 1.0f) + 1.0f;  o.w = (v.w + 1.0f) + 1.0f;
        m = fmaxf(m, fmaxf(fmaxf(o.x, o.y), fmaxf(o.z, o.w)));
        out[i] = o;
    }

    // fp add of a constant is monotone non-decreasing, so (bit-exact):
    //   any((o+1)+1 >= 3)  <=>  ((max(o)+1)+1) >= 3
    bool ta = (m >= 3.0f);
    bool tb = (((m + 1.0f) + 1.0f) >= 3.0f);

    unsigned wa = __any_sync(0xFFFFFFFFu, ta);
    unsigned wb = __any_sync(0xFFFFFFFFu, tb);

    __shared__ unsigned char s_wf[WARPS];
    __shared__ unsigned long long s_final;  // final packed value, 0 if not last
    if ((t & 31) == 0)
        s_wf[t >> 5] = (unsigned char)((wa ? 1u : 0u) | (wb ? 2u : 0u));
    __syncthreads();

    if (t == 0) {
        unsigned f = 0;
#pragma unroll
        for (int w = 0; w < WARPS; w++) f |= s_wf[w];
        unsigned long long delta = 1ULL
                                 + ((f & 1u) ? A_INC : 0ULL)
                                 + ((f & 2u) ? B_INC : 0ULL);
        unsigned long long old = atomicAdd(&g_packed, delta);
        unsigned arrivals = (unsigned)(old & 0xFFFFULL) + 1u;
        s_final = (arrivals == gridDim.x) ? (old + delta) : 0ULL;
    }
    __syncthreads();

    unsigned long long fin = s_final;
    if (fin) {
        // Last-arriving block. All other blocks' deltas are in `fin`.
        bool any_a = ((fin >> 16) & 0xFFFFULL) != 0;
        bool any_b = ((fin >> 32) & 0xFFFFULL) != 0;

        if (!any_a) {
            // Rare path (statistically never for this input): the chain
            // survived checker #1 — rewrite output with deeper-chain values.
            // Reads only x, so no cross-block ordering on out[] is needed.
            bool five = !any_b;
            for (int j = t; j < n4; j += THREADS) {
                float4 v = x[j];
                float4 o;
                o.x = (((v.x + 1.0f) + 1.0f) + 1.0f) + 1.0f;
                o.y = (((v.y + 1.0f) + 1.0f) + 1.0f) + 1.0f;
                o.z = (((v.z + 1.0f) + 1.0f) + 1.0f) + 1.0f;
                o.w = (((v.w + 1.0f) + 1.0f) + 1.0f) + 1.0f;
                if (five) { o.x += 1.0f; o.y += 1.0f; o.z += 1.0f; o.w += 1.0f; }
                out[j] = o;
            }
        }

        // Reset for the next graph replay: all arrivals already happened
        // (we are last), and the next launch is ordered by the launch
        // boundary, so a plain store suffices.
        if (t == 0) g_packed = 0ULL;
    }
}

extern "C" void kernel_launch(void* const* d_in, const int* in_sizes, int n_in,
                              void* d_out, int out_size)
{
    const float4* x = (const float4*)d_in[0];
    float4* out = (float4*)d_out;
    int n = in_sizes[0];
    int n4 = n >> 2;  // 4096*8192 divisible by 4

    const int blocks = 148 * 8;  // one full wave (8 × 256 thr = 2048/SM), dense chunks
    scn_fused_kernel<<<blocks, THREADS>>>(x, out, n4);
}